// round 8
// baseline (speedup 1.0000x reference)
#include <cuda_runtime.h>

// Shapes (fixed for this problem)
#define BB   8
#define LL   200
#define HIDD 256
#define NH   8
#define DHH  32
#define NEGV (-4294967295.0f)   // -2^32 + 1, matches reference padding value

// Scratch (device globals: allocation-free rule)
__device__ float g_Qp[BB * LL * HIDD];
__device__ float g_Ks[BB * LL * HIDD];   // K-proj + abs_pos_K  (folded)
__device__ float g_Vs[BB * LL * HIDD];   // V-proj + abs_pos_V  (folded)

// ---------------------------------------------------------------------------
// Projection GEMM:  Y = X @ W^T + bias (+ optional abs_pos fold)
// M=1600, N=256, K=256.  grid (25, 4, 3): z selects Q/K/V. block = 256 thr.
// Tiles: BM=BN=64, BK=16; 4x4 register micro-tile per thread.
// ---------------------------------------------------------------------------
__global__ __launch_bounds__(256) void proj_kernel(
    const float* __restrict__ queries, const float* __restrict__ keys,
    const float* __restrict__ Wq, const float* __restrict__ bq,
    const float* __restrict__ Wk, const float* __restrict__ bk,
    const float* __restrict__ Wv, const float* __restrict__ bv,
    const float* __restrict__ apK, const float* __restrict__ apV)
{
    const int which = blockIdx.z;
    const float* X    = (which == 0) ? queries : keys;
    const float* W    = (which == 0) ? Wq : (which == 1) ? Wk : Wv;
    const float* bias = (which == 0) ? bq : (which == 1) ? bk : bv;
    const float* fold = (which == 0) ? (const float*)0 : (which == 1) ? apK : apV;
    float* Y          = (which == 0) ? g_Qp : (which == 1) ? g_Ks : g_Vs;

    __shared__ float As[16][65];   // [k][m], padded
    __shared__ float Bs[16][65];   // [k][n], padded

    const int tid = threadIdx.x;
    const int tx = tid & 15, ty = tid >> 4;
    const int row0 = blockIdx.x * 64, col0 = blockIdx.y * 64;

    const int lr  = tid >> 2;          // 0..63 (tile row to load)
    const int lc4 = (tid & 3) * 4;     // 0,4,8,12 (k-offset)

    float acc[4][4] = {};

    for (int kt = 0; kt < HIDD; kt += 16) {
        float4 av = *(const float4*)&X[(row0 + lr) * HIDD + kt + lc4];
        float4 bv4 = *(const float4*)&W[(col0 + lr) * HIDD + kt + lc4];
        As[lc4 + 0][lr] = av.x;  As[lc4 + 1][lr] = av.y;
        As[lc4 + 2][lr] = av.z;  As[lc4 + 3][lr] = av.w;
        Bs[lc4 + 0][lr] = bv4.x; Bs[lc4 + 1][lr] = bv4.y;
        Bs[lc4 + 2][lr] = bv4.z; Bs[lc4 + 3][lr] = bv4.w;
        __syncthreads();
        #pragma unroll
        for (int kk = 0; kk < 16; kk++) {
            float a[4], b[4];
            #pragma unroll
            for (int i = 0; i < 4; i++) a[i] = As[kk][ty * 4 + i];
            #pragma unroll
            for (int j = 0; j < 4; j++) b[j] = Bs[kk][tx * 4 + j];
            #pragma unroll
            for (int i = 0; i < 4; i++)
                #pragma unroll
                for (int j = 0; j < 4; j++)
                    acc[i][j] += a[i] * b[j];
        }
        __syncthreads();
    }

    #pragma unroll
    for (int i = 0; i < 4; i++) {
        const int r = row0 + ty * 4 + i;
        #pragma unroll
        for (int j = 0; j < 4; j++) {
            const int cc = col0 + tx * 4 + j;
            float v = acc[i][j] + bias[cc];
            if (fold) v += fold[r * HIDD + cc];
            Y[r * HIDD + cc] = v;
        }
    }
}

// ---------------------------------------------------------------------------
// Attention: one CTA per (q, b). 256 threads: warp w = head w, lane d = dim.
// logit(h,q,k) = Q_h . (Ksum + TMk_slice)_h / sqrt(DH)   [Pk folded into Ksum]
// out(h,q,d)   = sum_k a(h,k) * (Vsum + TMv_slice)        [Pv folded into Vsum]
// Masked (q,k): skip TMk read entirely; V-side skips k when a(k) == 0 exactly.
// ---------------------------------------------------------------------------
__global__ __launch_bounds__(256) void attn_kernel(
    const float* __restrict__ tmK, const float* __restrict__ tmV,
    const int* __restrict__ time_mask, const int* __restrict__ attn_mask,
    float* __restrict__ out)
{
    const int q = blockIdx.x;
    const int b = blockIdx.y;
    const int c = threadIdx.x;     // channel 0..255
    const int w = c >> 5;          // head
    const int d = c & 31;          // lane within head

    __shared__ float aw[NH][LL];
    __shared__ int   mrow[LL];

    // Build combined mask row (nonzero 32-bit word == true; works for both
    // int32 and float32 encodings of the bool inputs)
    const int tmw = time_mask[b * LL + q];
    for (int k = c; k < LL; k += 256)
        mrow[k] = (tmw != 0) | (attn_mask[q * LL + k] != 0);
    __syncthreads();

    const float qv = g_Qp[(b * LL + q) * HIDD + c];
    const float* __restrict__ Krow  = g_Ks + (size_t)(b * LL) * HIDD;
    const float* __restrict__ TMKr  = tmK + (size_t)(b * LL + q) * LL * HIDD;
    const float  scale = 0.17677669529663687f;   // 1/sqrt(32)

    // ---- Phase 1: logits ----
    #pragma unroll 2
    for (int k = 0; k < LL; k++) {
        float logit;
        if (mrow[k]) {
            logit = NEGV;
        } else {
            float p = qv * (Krow[k * HIDD + c] + TMKr[(size_t)k * HIDD + c]);
            #pragma unroll
            for (int o = 16; o > 0; o >>= 1)
                p += __shfl_xor_sync(0xffffffffu, p, o);
            logit = p * scale;
        }
        if (d == 0) aw[w][k] = logit;
    }
    __syncthreads();

    // ---- Phase 2: per-head softmax (warp-local over LL logits) ----
    {
        float vals[7];
        float mx = -3.402823466e38f;
        #pragma unroll
        for (int i = 0; i < 7; i++) {
            const int k = d + 32 * i;
            float v = (k < LL) ? aw[w][k] : -3.402823466e38f;
            vals[i] = v;
            mx = fmaxf(mx, v);
        }
        #pragma unroll
        for (int o = 16; o > 0; o >>= 1)
            mx = fmaxf(mx, __shfl_xor_sync(0xffffffffu, mx, o));
        float s = 0.f;
        #pragma unroll
        for (int i = 0; i < 7; i++) {
            const int k = d + 32 * i;
            if (k < LL) { vals[i] = __expf(vals[i] - mx); s += vals[i]; }
        }
        #pragma unroll
        for (int o = 16; o > 0; o >>= 1)
            s += __shfl_xor_sync(0xffffffffu, s, o);
        const float inv = 1.0f / s;
        #pragma unroll
        for (int i = 0; i < 7; i++) {
            const int k = d + 32 * i;
            if (k < LL) aw[w][k] = vals[i] * inv;
        }
    }
    __syncthreads();

    // ---- Phase 3: weighted value accumulation ----
    const float* __restrict__ Vrow = g_Vs + (size_t)(b * LL) * HIDD;
    const float* __restrict__ TMVr = tmV + (size_t)(b * LL + q) * LL * HIDD;
    float acc = 0.f;
    #pragma unroll 4
    for (int k = 0; k < LL; k++) {
        const float wgt = aw[w][k];
        if (wgt != 0.f)   // exp underflows to exactly 0 for masked entries
            acc += wgt * (Vrow[k * HIDD + c] + TMVr[(size_t)k * HIDD + c]);
    }
    out[(b * LL + q) * HIDD + c] = acc;
}

// ---------------------------------------------------------------------------
extern "C" void kernel_launch(void* const* d_in, const int* in_sizes, int n_in,
                              void* d_out, int out_size)
{
    const float* queries   = (const float*)d_in[0];
    const float* keys      = (const float*)d_in[1];
    const int*   time_mask = (const int*)  d_in[2];
    const int*   attn_mask = (const int*)  d_in[3];
    const float* tmK       = (const float*)d_in[4];
    const float* tmV       = (const float*)d_in[5];
    const float* apK       = (const float*)d_in[6];
    const float* apV       = (const float*)d_in[7];
    // d_in[8] = time_attn (unused by the forward pass)
    const float* Wq        = (const float*)d_in[9];
    const float* bq        = (const float*)d_in[10];
    const float* Wk        = (const float*)d_in[11];
    const float* bk        = (const float*)d_in[12];
    const float* Wv        = (const float*)d_in[13];
    const float* bv        = (const float*)d_in[14];
    float* out = (float*)d_out;

    dim3 pgrid(1600 / 64, HIDD / 64, 3);   // (25, 4, 3)
    proj_kernel<<<pgrid, 256>>>(queries, keys, Wq, bq, Wk, bk, Wv, bv, apK, apV);

    dim3 agrid(LL, BB);                     // (200, 8)
    attn_kernel<<<agrid, 256>>>(tmK, tmV, time_mask, attn_mask, out);
}

// round 9
// speedup vs baseline: 2.0574x; 2.0574x over previous
#include <cuda_runtime.h>

// Shapes (fixed for this problem)
#define BB   8
#define LL   200
#define HIDD 256
#define NH   8
#define DHH  32
#define NEGV (-4294967295.0f)   // -2^32 + 1, matches reference padding value

// Scratch (device globals: allocation-free rule)
__device__ float g_Qp[BB * LL * HIDD];
__device__ float g_Ks[BB * LL * HIDD];   // K-proj + abs_pos_K  (folded)
__device__ float g_Vs[BB * LL * HIDD];   // V-proj + abs_pos_V  (folded)

// ---------------------------------------------------------------------------
// Projection GEMM:  Y = X @ W^T + bias (+ optional abs_pos fold)
// M=1600, N=256, K=256.  grid (25, 4, 3): z selects Q/K/V. block = 256 thr.
// ---------------------------------------------------------------------------
__global__ __launch_bounds__(256) void proj_kernel(
    const float* __restrict__ queries, const float* __restrict__ keys,
    const float* __restrict__ Wq, const float* __restrict__ bq,
    const float* __restrict__ Wk, const float* __restrict__ bk,
    const float* __restrict__ Wv, const float* __restrict__ bv,
    const float* __restrict__ apK, const float* __restrict__ apV)
{
    const int which = blockIdx.z;
    const float* X    = (which == 0) ? queries : keys;
    const float* W    = (which == 0) ? Wq : (which == 1) ? Wk : Wv;
    const float* bias = (which == 0) ? bq : (which == 1) ? bk : bv;
    const float* fold = (which == 0) ? (const float*)0 : (which == 1) ? apK : apV;
    float* Y          = (which == 0) ? g_Qp : (which == 1) ? g_Ks : g_Vs;

    __shared__ float As[16][65];   // [k][m], padded
    __shared__ float Bs[16][65];   // [k][n], padded

    const int tid = threadIdx.x;
    const int tx = tid & 15, ty = tid >> 4;
    const int row0 = blockIdx.x * 64, col0 = blockIdx.y * 64;

    const int lr  = tid >> 2;          // 0..63 (tile row to load)
    const int lc4 = (tid & 3) * 4;     // 0,4,8,12 (k-offset)

    float acc[4][4] = {};

    for (int kt = 0; kt < HIDD; kt += 16) {
        float4 av  = *(const float4*)&X[(row0 + lr) * HIDD + kt + lc4];
        float4 bv4 = *(const float4*)&W[(col0 + lr) * HIDD + kt + lc4];
        As[lc4 + 0][lr] = av.x;  As[lc4 + 1][lr] = av.y;
        As[lc4 + 2][lr] = av.z;  As[lc4 + 3][lr] = av.w;
        Bs[lc4 + 0][lr] = bv4.x; Bs[lc4 + 1][lr] = bv4.y;
        Bs[lc4 + 2][lr] = bv4.z; Bs[lc4 + 3][lr] = bv4.w;
        __syncthreads();
        #pragma unroll
        for (int kk = 0; kk < 16; kk++) {
            float a[4], b[4];
            #pragma unroll
            for (int i = 0; i < 4; i++) a[i] = As[kk][ty * 4 + i];
            #pragma unroll
            for (int j = 0; j < 4; j++) b[j] = Bs[kk][tx * 4 + j];
            #pragma unroll
            for (int i = 0; i < 4; i++)
                #pragma unroll
                for (int j = 0; j < 4; j++)
                    acc[i][j] += a[i] * b[j];
        }
        __syncthreads();
    }

    #pragma unroll
    for (int i = 0; i < 4; i++) {
        const int r = row0 + ty * 4 + i;
        #pragma unroll
        for (int j = 0; j < 4; j++) {
            const int cc = col0 + tx * 4 + j;
            float v = acc[i][j] + bias[cc];
            if (fold) v += fold[r * HIDD + cc];
            Y[r * HIDD + cc] = v;
        }
    }
}

// ---------------------------------------------------------------------------
// Attention: one CTA per (q, b). 256 threads.
// Phase 1: warp w handles k = w + 8i; each lane holds 2 float4 (full 1KB row
//   coalesced). 32-dim head dots via 8-lane segmented shuffle reduction; one
//   pass yields all 8 heads' logits for that k. Masked k: skip TMk load.
// Phase 2: per-head softmax, warp-local.
// Phase 3: thread owns float4 channel group j (j=tid&63), k strided mod 4
//   (kq=tid>>6); float4 loads, zero-weight k skipped; 4-way smem reduction.
// ---------------------------------------------------------------------------
__global__ __launch_bounds__(256) void attn_kernel(
    const float* __restrict__ tmK, const float* __restrict__ tmV,
    const int* __restrict__ time_mask, const int* __restrict__ attn_mask,
    float* __restrict__ out)
{
    const int q = blockIdx.x;
    const int b = blockIdx.y;
    const int tid = threadIdx.x;
    const int w = tid >> 5;        // warp
    const int l = tid & 31;        // lane

    __shared__ float aw[NH][LL];
    __shared__ int   mrow[LL];
    __shared__ float4 red[4][64];

    // Combined mask row (nonzero word == true)
    const int tmw = time_mask[b * LL + q];
    for (int k = tid; k < LL; k += 256)
        mrow[k] = (tmw != 0) | (attn_mask[q * LL + k] != 0);
    __syncthreads();

    const float* __restrict__ Qp = g_Qp + (size_t)(b * LL + q) * HIDD;
    const float4 q0 = *(const float4*)(Qp + 4 * l);
    const float4 q1 = *(const float4*)(Qp + 128 + 4 * l);

    const float* __restrict__ Ks  = g_Ks + (size_t)(b * LL) * HIDD;
    const float* __restrict__ TMK = tmK + (size_t)(b * LL + q) * LL * HIDD;
    const float  scale = 0.17677669529663687f;   // 1/sqrt(32)

    const int  seg = l >> 3;           // 0..3: p0 -> head seg, p1 -> head 4+seg
    const bool wr  = (l & 7) == 0;

    // ---- Phase 1: logits (25 k's per warp) ----
    #pragma unroll 2
    for (int i = 0; i < LL / 8; i++) {
        const int k = w + 8 * i;
        if (mrow[k]) {
            if (wr) { aw[seg][k] = NEGV; aw[4 + seg][k] = NEGV; }
        } else {
            const float4 a0 = *(const float4*)(Ks + k * HIDD + 4 * l);
            const float4 a1 = *(const float4*)(Ks + k * HIDD + 128 + 4 * l);
            const float4 t0 = *(const float4*)(TMK + (size_t)k * HIDD + 4 * l);
            const float4 t1 = *(const float4*)(TMK + (size_t)k * HIDD + 128 + 4 * l);
            float p0 = q0.x * (a0.x + t0.x) + q0.y * (a0.y + t0.y)
                     + q0.z * (a0.z + t0.z) + q0.w * (a0.w + t0.w);
            float p1 = q1.x * (a1.x + t1.x) + q1.y * (a1.y + t1.y)
                     + q1.z * (a1.z + t1.z) + q1.w * (a1.w + t1.w);
            p0 += __shfl_xor_sync(0xffffffffu, p0, 1);
            p0 += __shfl_xor_sync(0xffffffffu, p0, 2);
            p0 += __shfl_xor_sync(0xffffffffu, p0, 4);
            p1 += __shfl_xor_sync(0xffffffffu, p1, 1);
            p1 += __shfl_xor_sync(0xffffffffu, p1, 2);
            p1 += __shfl_xor_sync(0xffffffffu, p1, 4);
            if (wr) { aw[seg][k] = p0 * scale; aw[4 + seg][k] = p1 * scale; }
        }
    }
    __syncthreads();

    // ---- Phase 2: per-head softmax (warp w = head w) ----
    {
        float vals[7];
        float mx = -3.402823466e38f;
        #pragma unroll
        for (int i = 0; i < 7; i++) {
            const int k = l + 32 * i;
            float v = (k < LL) ? aw[w][k] : -3.402823466e38f;
            vals[i] = v;
            mx = fmaxf(mx, v);
        }
        #pragma unroll
        for (int o = 16; o > 0; o >>= 1)
            mx = fmaxf(mx, __shfl_xor_sync(0xffffffffu, mx, o));
        float s = 0.f;
        #pragma unroll
        for (int i = 0; i < 7; i++) {
            const int k = l + 32 * i;
            if (k < LL) { vals[i] = __expf(vals[i] - mx); s += vals[i]; }
        }
        #pragma unroll
        for (int o = 16; o > 0; o >>= 1)
            s += __shfl_xor_sync(0xffffffffu, s, o);
        const float inv = 1.0f / s;
        #pragma unroll
        for (int i = 0; i < 7; i++) {
            const int k = l + 32 * i;
            if (k < LL) aw[w][k] = vals[i] * inv;
        }
    }
    __syncthreads();

    // ---- Phase 3: weighted value accumulation (float4 per thread) ----
    const int j  = tid & 63;       // channel group: channels [4j, 4j+4)
    const int kq = tid >> 6;       // k offset mod 4 (uniform per warp)
    const int h3 = j >> 3;         // head of channels 4j..4j+3
    const float* __restrict__ Vs  = g_Vs + (size_t)(b * LL) * HIDD;
    const float* __restrict__ TMV = tmV + (size_t)(b * LL + q) * LL * HIDD;

    float4 acc = make_float4(0.f, 0.f, 0.f, 0.f);
    #pragma unroll 4
    for (int i = 0; i < LL / 4; i++) {
        const int k = kq + 4 * i;
        const float wgt = aw[h3][k];
        if (wgt != 0.f) {          // exp underflows to exactly 0 when masked
            const float4 v = *(const float4*)(Vs + k * HIDD + 4 * j);
            const float4 t = *(const float4*)(TMV + (size_t)k * HIDD + 4 * j);
            acc.x += wgt * (v.x + t.x);
            acc.y += wgt * (v.y + t.y);
            acc.z += wgt * (v.z + t.z);
            acc.w += wgt * (v.w + t.w);
        }
    }
    red[kq][j] = acc;
    __syncthreads();
    if (kq == 0) {
        const float4 r1 = red[1][j], r2 = red[2][j], r3 = red[3][j];
        acc.x += r1.x + r2.x + r3.x;
        acc.y += r1.y + r2.y + r3.y;
        acc.z += r1.z + r2.z + r3.z;
        acc.w += r1.w + r2.w + r3.w;
        *(float4*)(out + (size_t)(b * LL + q) * HIDD + 4 * j) = acc;
    }
}

// ---------------------------------------------------------------------------
extern "C" void kernel_launch(void* const* d_in, const int* in_sizes, int n_in,
                              void* d_out, int out_size)
{
    const float* queries   = (const float*)d_in[0];
    const float* keys      = (const float*)d_in[1];
    const int*   time_mask = (const int*)  d_in[2];
    const int*   attn_mask = (const int*)  d_in[3];
    const float* tmK       = (const float*)d_in[4];
    const float* tmV       = (const float*)d_in[5];
    const float* apK       = (const float*)d_in[6];
    const float* apV       = (const float*)d_in[7];
    // d_in[8] = time_attn (unused by the forward pass)
    const float* Wq        = (const float*)d_in[9];
    const float* bq        = (const float*)d_in[10];
    const float* Wk        = (const float*)d_in[11];
    const float* bk        = (const float*)d_in[12];
    const float* Wv        = (const float*)d_in[13];
    const float* bv        = (const float*)d_in[14];
    float* out = (float*)d_out;

    dim3 pgrid(1600 / 64, HIDD / 64, 3);   // (25, 4, 3)
    proj_kernel<<<pgrid, 256>>>(queries, keys, Wq, bq, Wk, bk, Wv, bv, apK, apV);

    dim3 agrid(LL, BB);                     // (200, 8)
    attn_kernel<<<agrid, 256>>>(tmK, tmV, time_mask, attn_mask, out);
}